// round 1
// baseline (speedup 1.0000x reference)
#include <cuda_runtime.h>
#include <cstdint>

// S4D Vandermonde kernel:  K[h,l] = 2 * sum_n C_eff[h,n] * exp(dtA[h,n] * l)
// H=256, NH=N/2=32, L=16384.
//
// Strategy: per (h, l-tile) block. 32 leader threads compute per-n coefficients
// (c_n, dtA_n, rstep_n = exp(dtA_n * TPB)) into shared. Each thread owns T
// strided l-values (l = l0 + tid + j*TPB, coalesced stores), seeds
// p_n = exp(dtA_n * (l0+tid)) once via MUFU, then runs a packed-f32x2
// multiply/accumulate recurrence: acc += c*p; p *= rstep.  (fma.rn.f32x2 /
// mul.rn.f32x2 are the sm_100+ dual-rate FFMA2 path.)

#define TPB 256
#define NH  32
#define T   16

__device__ __forceinline__ unsigned long long fma2(unsigned long long a,
                                                   unsigned long long b,
                                                   unsigned long long c) {
    unsigned long long d;
    asm("fma.rn.f32x2 %0, %1, %2, %3;" : "=l"(d) : "l"(a), "l"(b), "l"(c));
    return d;
}
__device__ __forceinline__ unsigned long long mul2(unsigned long long a,
                                                   unsigned long long b) {
    unsigned long long d;
    asm("mul.rn.f32x2 %0, %1, %2;" : "=l"(d) : "l"(a), "l"(b));
    return d;
}
__device__ __forceinline__ unsigned long long pack2(float lo, float hi) {
    unsigned long long u;
    asm("mov.b64 %0, {%1, %2};" : "=l"(u) : "f"(lo), "f"(hi));
    return u;
}
__device__ __forceinline__ void unpack2(unsigned long long u, float& lo, float& hi) {
    asm("mov.b64 {%0, %1}, %2;" : "=f"(lo), "=f"(hi) : "l"(u));
}

__global__ void __launch_bounds__(TPB, 2) s4d_kernel(
    const float* __restrict__ log_dt,      // [H]
    const float* __restrict__ C,           // [H, NH]
    const float* __restrict__ log_A_real,  // [H, NH]
    const float* __restrict__ A_imag,      // [H, NH]
    float* __restrict__ out,               // [H, L]
    int L)
{
    const int h  = blockIdx.y;
    const int l0 = blockIdx.x * (TPB * T);
    const int t  = threadIdx.x;

    __shared__ float s_c[NH];     // 2 * C_eff
    __shared__ float s_dtA[NH];   // dtA_n
    __shared__ float s_r[NH];     // exp(dtA_n * TPB)  (per-step ratio, stride TPB)

    if (t < NH) {
        float dt   = expf(log_dt[h]);
        float Ar   = -expf(log_A_real[h * NH + t]);
        float Ai   = A_imag[h * NH + t];
        float dtA  = Ar * dt;
        float den  = Ar * Ar + Ai * Ai;
        // exactly mirrors reference fp32 math: C*(exp(dtA)-1)*Ar/den, times 2
        s_c[t]   = 2.0f * C[h * NH + t] * (expf(dtA) - 1.0f) * Ar / den;
        s_dtA[t] = dtA;
        s_r[t]   = expf(dtA * (float)TPB);
    }
    __syncthreads();

    // Seed p_n = exp(dtA_n * l_start), pack state as f32x2 pairs.
    const float lstart = (float)(l0 + t);
    unsigned long long p[NH / 2], r[NH / 2], c[NH / 2];
#pragma unroll
    for (int i = 0; i < NH / 2; i++) {
        float p0 = __expf(s_dtA[2 * i]     * lstart);
        float p1 = __expf(s_dtA[2 * i + 1] * lstart);
        p[i] = pack2(p0, p1);
        r[i] = pack2(s_r[2 * i], s_r[2 * i + 1]);
        c[i] = pack2(s_c[2 * i], s_c[2 * i + 1]);
    }

    float* o = out + (size_t)h * L + l0 + t;
    const int lim = L - l0 - t;   // handles any L not divisible by tile

#pragma unroll
    for (int j = 0; j < T; j++) {
        unsigned long long acc = 0ull;   // (+0.0f, +0.0f)
#pragma unroll
        for (int i = 0; i < NH / 2; i++) {
            acc  = fma2(c[i], p[i], acc);
            p[i] = mul2(p[i], r[i]);
        }
        float ax, ay;
        unpack2(acc, ax, ay);
        if (j * TPB < lim) o[j * TPB] = ax + ay;
    }
}

extern "C" void kernel_launch(void* const* d_in, const int* in_sizes, int n_in,
                              void* d_out, int out_size)
{
    const float* log_dt     = (const float*)d_in[0];
    const float* C          = (const float*)d_in[1];
    const float* log_A_real = (const float*)d_in[2];
    const float* A_imag     = (const float*)d_in[3];
    float* out = (float*)d_out;

    const int H = in_sizes[0];
    const int L = out_size / H;

    dim3 grid((L + TPB * T - 1) / (TPB * T), H);
    s4d_kernel<<<grid, TPB>>>(log_dt, C, log_A_real, A_imag, out, L);
}

// round 2
// speedup vs baseline: 1.9706x; 1.9706x over previous
#include <cuda_runtime.h>
#include <cstdint>

// S4D Vandermonde kernel:  K[h,l] = 2 * sum_n C_eff[h,n] * exp(dtA[h,n] * l)
// H=256, NH=N/2=32, L=16384.
//
// Key structural observation: with this problem's init, log_A_real is a
// constant (log 0.5) across (h, n), so dtA[h,n] = A_real*dt[h] is constant
// across n.  Then K[h,l] = (sum_n c_n) * exp(dtA*l): one geometric recurrence
// per head -> pure store-bandwidth kernel (float4 stores, 1 mul2 pair per 4
// outputs).  We verify this uniformity AT RUNTIME (bitwise equality across n,
// which holds exactly when the inputs are bitwise-identical) and fall back to
// the generic 32-chain packed-f32x2 recurrence otherwise.

#define TPB  256
#define NH   32
#define TILE 4096          // l-elements per block (both paths)
#define TG   16            // generic path: strided elems/thread
#define JF   4             // fast path: 4 float4 stores/thread (4*4*256 = 4096)

__device__ __forceinline__ unsigned long long fma2(unsigned long long a,
                                                   unsigned long long b,
                                                   unsigned long long c) {
    unsigned long long d;
    asm("fma.rn.f32x2 %0, %1, %2, %3;" : "=l"(d) : "l"(a), "l"(b), "l"(c));
    return d;
}
__device__ __forceinline__ unsigned long long mul2(unsigned long long a,
                                                   unsigned long long b) {
    unsigned long long d;
    asm("mul.rn.f32x2 %0, %1, %2;" : "=l"(d) : "l"(a), "l"(b));
    return d;
}
__device__ __forceinline__ unsigned long long pack2(float lo, float hi) {
    unsigned long long u;
    asm("mov.b64 %0, {%1, %2};" : "=l"(u) : "f"(lo), "f"(hi));
    return u;
}
__device__ __forceinline__ void unpack2(unsigned long long u, float& lo, float& hi) {
    asm("mov.b64 {%0, %1}, %2;" : "=f"(lo), "=f"(hi) : "l"(u));
}

__global__ void __launch_bounds__(TPB) s4d_kernel(
    const float* __restrict__ log_dt,      // [H]
    const float* __restrict__ C,           // [H, NH]
    const float* __restrict__ log_A_real,  // [H, NH]
    const float* __restrict__ A_imag,      // [H, NH]
    float* __restrict__ out,               // [H, L]
    int L)
{
    const int h  = blockIdx.y;
    const int l0 = blockIdx.x * TILE;
    const int t  = threadIdx.x;

    __shared__ float s_c[NH];     // 2 * C_eff per n
    __shared__ float s_dtA[NH];   // dtA per n

    if (t < NH) {
        float dt   = expf(log_dt[h]);
        float Ar   = -expf(log_A_real[h * NH + t]);
        float Ai   = A_imag[h * NH + t];
        float dtA  = Ar * dt;
        float den  = Ar * Ar + Ai * Ai;
        // exactly mirrors reference fp32 math: 2*C*(exp(dtA)-1)*Ar/den
        s_c[t]   = 2.0f * C[h * NH + t] * (expf(dtA) - 1.0f) * Ar / den;
        s_dtA[t] = dtA;
    }
    __syncthreads();

    // Every thread checks n-uniformity of dtA and folds the coefficient sum.
    // (All reads are broadcast LDS — cheap.)
    const float dtA0 = s_dtA[0];
    float S = 0.0f;
    bool uniform = true;
#pragma unroll
    for (int i = 0; i < NH; i++) {
        S += s_c[i];
        uniform &= (__float_as_uint(s_dtA[i]) == __float_as_uint(dtA0));
    }

    if (uniform) {
        // ---------- fast path: K[h,l] = S * exp(dtA0 * l) ----------
        // thread t owns 4 contiguous floats at l0 + 4t + j*(4*TPB), j<4.
        const float lb  = (float)(l0 + 4 * t);
        const float q1  = __expf(dtA0);                 // ratio between adjacent l
        const float stp = __expf(dtA0 * (float)(4 * TPB)); // ratio between j-steps
        float p0 = __expf(dtA0 * lb);
        float p1 = p0 * q1;
        float p2 = p1 * q1;
        float p3 = p2 * q1;

        unsigned long long pa = pack2(p0, p1);
        unsigned long long pb = pack2(p2, p3);
        const unsigned long long s2  = pack2(S, S);
        const unsigned long long st2 = pack2(stp, stp);

        float4* o = (float4*)(out + (size_t)h * L + l0) + t;
#pragma unroll
        for (int j = 0; j < JF; j++) {
            unsigned long long va = mul2(pa, s2);
            unsigned long long vb = mul2(pb, s2);
            float4 v;
            unpack2(va, v.x, v.y);
            unpack2(vb, v.z, v.w);
            if (l0 + 4 * t + j * 4 * TPB + 3 < L) o[j * TPB] = v;
            pa = mul2(pa, st2);
            pb = mul2(pb, st2);
        }
    } else {
        // ---------- generic path: 32 independent geometric chains ----------
        const float lstart = (float)(l0 + t);
        unsigned long long p[NH / 2], r[NH / 2], c[NH / 2];
#pragma unroll
        for (int i = 0; i < NH / 2; i++) {
            float d0 = s_dtA[2 * i], d1 = s_dtA[2 * i + 1];
            p[i] = pack2(__expf(d0 * lstart), __expf(d1 * lstart));
            r[i] = pack2(__expf(d0 * (float)TPB), __expf(d1 * (float)TPB));
            c[i] = pack2(s_c[2 * i], s_c[2 * i + 1]);
        }

        float* o = out + (size_t)h * L + l0 + t;
        const int lim = L - l0 - t;
#pragma unroll
        for (int j = 0; j < TG; j++) {
            // 4 split accumulators to break the serial FFMA2 chain
            unsigned long long a0 = 0ull, a1 = 0ull, a2 = 0ull, a3 = 0ull;
#pragma unroll
            for (int i = 0; i < NH / 2; i += 4) {
                a0   = fma2(c[i],     p[i],     a0);
                p[i]     = mul2(p[i],     r[i]);
                a1   = fma2(c[i + 1], p[i + 1], a1);
                p[i + 1] = mul2(p[i + 1], r[i + 1]);
                a2   = fma2(c[i + 2], p[i + 2], a2);
                p[i + 2] = mul2(p[i + 2], r[i + 2]);
                a3   = fma2(c[i + 3], p[i + 3], a3);
                p[i + 3] = mul2(p[i + 3], r[i + 3]);
            }
            float x0, y0, x1, y1, x2, y2, x3, y3;
            unpack2(a0, x0, y0); unpack2(a1, x1, y1);
            unpack2(a2, x2, y2); unpack2(a3, x3, y3);
            float v = ((x0 + y0) + (x1 + y1)) + ((x2 + y2) + (x3 + y3));
            if (j * TPB < lim) o[j * TPB] = v;
        }
    }
}

extern "C" void kernel_launch(void* const* d_in, const int* in_sizes, int n_in,
                              void* d_out, int out_size)
{
    const float* log_dt     = (const float*)d_in[0];
    const float* C          = (const float*)d_in[1];
    const float* log_A_real = (const float*)d_in[2];
    const float* A_imag     = (const float*)d_in[3];
    float* out = (float*)d_out;

    const int H = in_sizes[0];
    const int L = out_size / H;

    dim3 grid((L + TILE - 1) / TILE, H);
    s4d_kernel<<<grid, TPB>>>(log_dt, C, log_A_real, A_imag, out, L);
}

// round 3
// speedup vs baseline: 1.9779x; 1.0037x over previous
#include <cuda_runtime.h>
#include <cstdint>

// S4D Vandermonde kernel:  K[h,l] = 2 * sum_n C_eff[h,n] * exp(dtA[h,n] * l)
// H=256, NH=N/2=32, L=16384.
//
// Structure: with this problem's init, dtA[h,n] is constant across n, so
// K[h,l] = S[h] * exp(dtA[h]*l): a single geometric recurrence per head ->
// pure store-bandwidth kernel.  Uniformity is verified AT RUNTIME (bitwise,
// warp ballot in warp 0 only) with a generic 32-chain fallback.
// R3 change: all per-head reduction/setup lives in warp 0 (ballot + shfl
// reduce + precomputed ratios), so worker threads do 1 MUFU exp + 8 mul2 +
// 4 STG.128 each -- prologue issue work cut ~4x vs R2.

#define TPB  256
#define NH   32
#define TILE 4096          // l-elements per block
#define TG   16            // generic path: strided elems/thread
#define JF   4             // fast path: 4 float4 stores/thread (4*4*256=4096)

__device__ __forceinline__ unsigned long long fma2(unsigned long long a,
                                                   unsigned long long b,
                                                   unsigned long long c) {
    unsigned long long d;
    asm("fma.rn.f32x2 %0, %1, %2, %3;" : "=l"(d) : "l"(a), "l"(b), "l"(c));
    return d;
}
__device__ __forceinline__ unsigned long long mul2(unsigned long long a,
                                                   unsigned long long b) {
    unsigned long long d;
    asm("mul.rn.f32x2 %0, %1, %2;" : "=l"(d) : "l"(a), "l"(b));
    return d;
}
__device__ __forceinline__ unsigned long long pack2(float lo, float hi) {
    unsigned long long u;
    asm("mov.b64 %0, {%1, %2};" : "=l"(u) : "f"(lo), "f"(hi));
    return u;
}
__device__ __forceinline__ void unpack2(unsigned long long u, float& lo, float& hi) {
    asm("mov.b64 {%0, %1}, %2;" : "=f"(lo), "=f"(hi) : "l"(u));
}

__global__ void __launch_bounds__(TPB) s4d_kernel(
    const float* __restrict__ log_dt,      // [H]
    const float* __restrict__ C,           // [H, NH]
    const float* __restrict__ log_A_real,  // [H, NH]
    const float* __restrict__ A_imag,      // [H, NH]
    float* __restrict__ out,               // [H, L]
    int L)
{
    const int h  = blockIdx.y;
    const int l0 = blockIdx.x * TILE;
    const int t  = threadIdx.x;

    __shared__ float s_c[NH];     // per-n coeff (generic path)
    __shared__ float s_dtA[NH];   // per-n dtA   (generic path)
    __shared__ float s_S, s_dtA0, s_q1, s_stp;
    __shared__ int   s_uniform;

    if (t < NH) {   // warp 0 only
        float dt   = expf(log_dt[h]);
        float Ar   = -expf(log_A_real[h * NH + t]);
        float Ai   = A_imag[h * NH + t];
        float dtA  = Ar * dt;
        float den  = Ar * Ar + Ai * Ai;
        // exactly mirrors reference fp32 math: 2*C*(exp(dtA)-1)*Ar/den
        float c    = 2.0f * C[h * NH + t] * (expf(dtA) - 1.0f) * Ar / den;
        s_c[t]   = c;
        s_dtA[t] = dtA;

        float dtA0  = __shfl_sync(0xffffffffu, dtA, 0);
        unsigned eq = __ballot_sync(0xffffffffu,
                        __float_as_uint(dtA) == __float_as_uint(dtA0));
#pragma unroll
        for (int o = 16; o; o >>= 1)
            c += __shfl_xor_sync(0xffffffffu, c, o);
        if (t == 0) {
            s_S       = c;
            s_dtA0    = dtA0;
            s_q1      = __expf(dtA0);                       // adjacent-l ratio
            s_stp     = __expf(dtA0 * (float)(4 * TPB));    // j-step ratio
            s_uniform = (eq == 0xffffffffu);
        }
    }
    __syncthreads();

    if (s_uniform) {
        // ---------- fast path: K[h,l] = S * exp(dtA0 * l) ----------
        const float S    = s_S;
        const float dtA0 = s_dtA0;
        const float q1   = s_q1;
        const float stp  = s_stp;

        const float lb = (float)(l0 + 4 * t);
        float p0 = __expf(dtA0 * lb);        // the ONE per-thread MUFU exp
        float p1 = p0 * q1;
        float p2 = p1 * q1;
        float p3 = p2 * q1;

        unsigned long long pa = pack2(p0, p1);
        unsigned long long pb = pack2(p2, p3);
        const unsigned long long s2  = pack2(S, S);
        const unsigned long long st2 = pack2(stp, stp);

        float4* o = (float4*)(out + (size_t)h * L + l0) + t;
#pragma unroll
        for (int j = 0; j < JF; j++) {
            unsigned long long va = mul2(pa, s2);
            unsigned long long vb = mul2(pb, s2);
            float4 v;
            unpack2(va, v.x, v.y);
            unpack2(vb, v.z, v.w);
            if (l0 + 4 * t + j * 4 * TPB + 3 < L) o[j * TPB] = v;
            pa = mul2(pa, st2);
            pb = mul2(pb, st2);
        }
    } else {
        // ---------- generic path: 32 independent geometric chains ----------
        const float lstart = (float)(l0 + t);
        unsigned long long p[NH / 2], r[NH / 2], c[NH / 2];
#pragma unroll
        for (int i = 0; i < NH / 2; i++) {
            float d0 = s_dtA[2 * i], d1 = s_dtA[2 * i + 1];
            p[i] = pack2(__expf(d0 * lstart), __expf(d1 * lstart));
            r[i] = pack2(__expf(d0 * (float)TPB), __expf(d1 * (float)TPB));
            c[i] = pack2(s_c[2 * i], s_c[2 * i + 1]);
        }

        float* o = out + (size_t)h * L + l0 + t;
        const int lim = L - l0 - t;
#pragma unroll
        for (int j = 0; j < TG; j++) {
            unsigned long long a0 = 0ull, a1 = 0ull, a2 = 0ull, a3 = 0ull;
#pragma unroll
            for (int i = 0; i < NH / 2; i += 4) {
                a0       = fma2(c[i],     p[i],     a0);
                p[i]     = mul2(p[i],     r[i]);
                a1       = fma2(c[i + 1], p[i + 1], a1);
                p[i + 1] = mul2(p[i + 1], r[i + 1]);
                a2       = fma2(c[i + 2], p[i + 2], a2);
                p[i + 2] = mul2(p[i + 2], r[i + 2]);
                a3       = fma2(c[i + 3], p[i + 3], a3);
                p[i + 3] = mul2(p[i + 3], r[i + 3]);
            }
            float x0, y0, x1, y1, x2, y2, x3, y3;
            unpack2(a0, x0, y0); unpack2(a1, x1, y1);
            unpack2(a2, x2, y2); unpack2(a3, x3, y3);
            float v = ((x0 + y0) + (x1 + y1)) + ((x2 + y2) + (x3 + y3));
            if (j * TPB < lim) o[j * TPB] = v;
        }
    }
}

extern "C" void kernel_launch(void* const* d_in, const int* in_sizes, int n_in,
                              void* d_out, int out_size)
{
    const float* log_dt     = (const float*)d_in[0];
    const float* C          = (const float*)d_in[1];
    const float* log_A_real = (const float*)d_in[2];
    const float* A_imag     = (const float*)d_in[3];
    float* out = (float*)d_out;

    const int H = in_sizes[0];
    const int L = out_size / H;

    dim3 grid((L + TILE - 1) / TILE, H);
    s4d_kernel<<<grid, TPB>>>(log_dt, C, log_A_real, A_imag, out, L);
}